// round 14
// baseline (speedup 1.0000x reference)
#include <cuda_runtime.h>
#include <cuda_bf16.h>
#include <cuda_fp16.h>
#include <math_constants.h>
#include <cstdint>

// Problem constants
#define N_NODES 20000
#define N_PAD   20096          // 157 * 128
#define IN_CH   512
#define HC      512
#define E_EDGES 320000
#define E_LABEL 100000
#define ATTN_BLOCKS 5000       // 20000 nodes / (8 warps / 2 warps-per-node)
#define BN1_BLOCKS 128

// ---------------- scratch ----------------
__device__ __half g_xh [N_PAD * IN_CH];        // fp16 x
__device__ __half g_wth[2][IN_CH * HC];        // fp16 W^T [n][k]
__device__ float g_xr[N_PAD * HC];
__device__ __nv_bfloat16 g_xlb[N_PAD * HC];    // bf16 xl
__device__ __nv_bfloat16 g_outb[N_NODES * HC]; // bf16 node features after GAT
__device__ int   g_deg[N_NODES + 1];           // zero at start; scan self-resets it
__device__ int   g_off[N_NODES + 1];
__device__ int   g_cur[N_NODES];
__device__ int   g_csr_src[E_EDGES];
__device__ int   g_bsum[32];
__device__ int   g_c1, g_c2;                   // scan grid-barrier counters (zero-init, self-reset)
__device__ int   g_bn_cnt;
__device__ float g_ps [ATTN_BLOCKS * HC];
__device__ float g_pq [ATTN_BLOCKS * HC];
__device__ float g_ps1[BN1_BLOCKS * HC];
__device__ float g_pq1[BN1_BLOCKS * HC];
__device__ float g_scale[HC];
__device__ float g_shift[HC];

// ---------------- helpers ----------------
__device__ __forceinline__ uint32_t smem_u32(const void* p) {
    uint32_t a;
    asm("{ .reg .u64 t; cvta.to.shared.u64 t, %1; cvt.u32.u64 %0, t; }" : "=r"(a) : "l"(p));
    return a;
}
__device__ __forceinline__ void cp_async16(uint32_t sa, const void* ga) {
    asm volatile("cp.async.cg.shared.global [%0], [%1], 16;" :: "r"(sa), "l"(ga) : "memory");
}
__device__ __forceinline__ void cp_commit() {
    asm volatile("cp.async.commit_group;" ::: "memory");
}
__device__ __forceinline__ void cp_wait0() {
    asm volatile("cp.async.wait_group 0;" ::: "memory");
}
__device__ __forceinline__ void ldm_x4(uint32_t* r, uint32_t addr) {
    asm volatile("ldmatrix.sync.aligned.m8n8.x4.shared.b16 {%0,%1,%2,%3}, [%4];"
                 : "=r"(r[0]), "=r"(r[1]), "=r"(r[2]), "=r"(r[3]) : "r"(addr));
}
__device__ __forceinline__ void mma16816h(float* d, const uint32_t* a, const uint32_t* b) {
    asm volatile("mma.sync.aligned.m16n8k16.row.col.f32.f16.f16.f32 "
                 "{%0,%1,%2,%3}, {%4,%5,%6,%7}, {%8,%9}, {%0,%1,%2,%3};"
                 : "+f"(d[0]), "+f"(d[1]), "+f"(d[2]), "+f"(d[3])
                 : "r"(a[0]), "r"(a[1]), "r"(a[2]), "r"(a[3]), "r"(b[0]), "r"(b[1]));
}
__device__ __forceinline__ float bflo(uint32_t u) { return __uint_as_float(u << 16); }
__device__ __forceinline__ float bfhi(uint32_t u) { return __uint_as_float(u & 0xFFFF0000u); }
__device__ __forceinline__ uint32_t packbf(float a, float b) {
    __nv_bfloat162 t = __float22bfloat162_rn(make_float2(a, b));
    return *(uint32_t*)&t;
}

// ---------------- fused conversion + histogram ----------------
#define CONVX_BLOCKS (N_PAD * IN_CH / 4 / 256)      // 10048
#define CONVW_BLOCKS (2 * IN_CH * HC / 256)         // 2048
#define HIST_BLOCKS  ((E_EDGES + 255) / 256)        // 1250

__global__ void conv_fused_kernel(const float* __restrict__ x,
                                  const float* __restrict__ Wl,
                                  const float* __restrict__ Wr,
                                  const int* __restrict__ ei)
{
    int bid = blockIdx.x;
    if (bid < CONVX_BLOCKS) {
        int i4 = bid * 256 + threadIdx.x;
        int i = i4 * 4;
        int row = i >> 9;
        float4 v = (row < N_NODES) ? *(const float4*)(x + i) : make_float4(0.f, 0.f, 0.f, 0.f);
        __half2 h01 = __floats2half2_rn(v.x, v.y);
        __half2 h23 = __floats2half2_rn(v.z, v.w);
        *(uint2*)((char*)g_xh + i * 2) = make_uint2(*(uint32_t*)&h01, *(uint32_t*)&h23);
    } else if (bid < CONVX_BLOCKS + CONVW_BLOCKS) {
        int j = (bid - CONVX_BLOCKS) * 256 + threadIdx.x;
        int mat = j >> 18;
        int i = j & 0x3FFFF;                                // n*512 + k
        const float* W = mat ? Wr : Wl;
        int n = i >> 9, k = i & 511;
        g_wth[mat][i] = __float2half_rn(W[k * HC + n]);
    } else {
        // histogram: g_deg is zero at kernel entry (zero-init + scan self-reset)
        int e = (bid - CONVX_BLOCKS - CONVW_BLOCKS) * 256 + threadIdx.x;
        if (e < E_EDGES) atomicAdd(&g_deg[ei[E_EDGES + e]], 1);
    }
}

// ---------------- single-pass fp16 HMMA GEMM (R12 proven) ----------------
#define SMS 144                      // 128B row + 16B pad
#define TILE_BYTES (128 * SMS)       // 18432
#define STAGE_BYTES (2 * TILE_BYTES) // 36864 (A + B tile)
#define GSMEM_TOTAL (2 * STAGE_BYTES)// 73728

__global__ void __launch_bounds__(256, 2) gemm_tc_kernel()
{
    extern __shared__ __align__(16) char smem[];

    const int tid  = threadIdx.x;
    const int wid  = tid >> 5;
    const int lane = tid & 31;
    const int wm   = wid & 1;
    const int wn   = wid >> 1;

    const int m0  = blockIdx.y * 128;
    const int n0  = blockIdx.x * 128;
    const int mat = blockIdx.z;

    const __half* A = g_xh + (size_t)m0 * IN_CH;
    const __half* B = g_wth[mat] + (size_t)n0 * IN_CH;

    const uint32_t sb = smem_u32(smem);
    const int r0 = tid >> 3;          // 0..31
    const int c0 = tid & 7;           // 16B chunk (0..7) within 128B row

    float acc[4][4][4];
#pragma unroll
    for (int i = 0; i < 4; i++)
#pragma unroll
        for (int j = 0; j < 4; j++)
#pragma unroll
            for (int q = 0; q < 4; q++) acc[i][j][q] = 0.f;

    auto issue = [&](int kc, int stg) {
        const uint32_t base = sb + stg * STAGE_BYTES;
        const int kel = kc * 64 + c0 * 8;
#pragma unroll
        for (int j = 0; j < 4; j++) {
            int row = r0 + j * 32;
            uint32_t so = row * SMS + c0 * 16;
            size_t  go = (size_t)row * IN_CH + kel;
            cp_async16(base + so, A + go);
            cp_async16(base + TILE_BYTES + so, B + go);
        }
    };

    issue(0, 0); cp_commit();

    for (int kc = 0; kc < 8; kc++) {
        cp_wait0();
        __syncthreads();
        if (kc + 1 < 8) { issue(kc + 1, (kc + 1) & 1); cp_commit(); }

        const uint32_t base = sb + (kc & 1) * STAGE_BYTES;
#pragma unroll
        for (int ks = 0; ks < 4; ks++) {
            const int kb = ks * 32;
            uint32_t b[4][2];
#pragma unroll
            for (int nh = 0; nh < 2; nh++) {
                int row = wn * 32 + nh * 16 + (lane >> 4) * 8 + (lane & 7);
                uint32_t off = row * SMS + kb + ((lane >> 3) & 1) * 16;
                uint32_t t[4];
                ldm_x4(t, base + TILE_BYTES + off);
                b[nh * 2 + 0][0] = t[0]; b[nh * 2 + 0][1] = t[1];
                b[nh * 2 + 1][0] = t[2]; b[nh * 2 + 1][1] = t[3];
            }
            uint32_t a[4][4];
            {
                int row = wm * 64 + ((lane >> 3) & 1) * 8 + (lane & 7);
                uint32_t off = row * SMS + kb + ((lane >> 4) & 1) * 16;
                ldm_x4(a[0], base + off);
            }
#pragma unroll
            for (int mt = 0; mt < 4; mt++) {
                if (mt < 3) {
                    int row = wm * 64 + (mt + 1) * 16 + ((lane >> 3) & 1) * 8 + (lane & 7);
                    uint32_t off = row * SMS + kb + ((lane >> 4) & 1) * 16;
                    ldm_x4(a[mt + 1], base + off);
                }
#pragma unroll
                for (int nt = 0; nt < 4; nt++)
                    mma16816h(acc[mt][nt], a[mt], b[nt]);
            }
        }
    }

    const int g = lane >> 2;
    const int q = lane & 3;
#pragma unroll
    for (int mt = 0; mt < 4; mt++) {
#pragma unroll
        for (int nt = 0; nt < 4; nt++) {
            int row = m0 + wm * 64 + mt * 16 + g;
            int col = n0 + wn * 32 + nt * 8 + q * 2;
            if (mat == 0) {
                *(uint32_t*)&g_xlb[(size_t)row * HC + col] =
                    packbf(acc[mt][nt][0], acc[mt][nt][1]);
                *(uint32_t*)&g_xlb[(size_t)(row + 8) * HC + col] =
                    packbf(acc[mt][nt][2], acc[mt][nt][3]);
            } else {
                *(float2*)&g_xr[(size_t)row * HC + col] =
                    make_float2(acc[mt][nt][0], acc[mt][nt][1]);
                *(float2*)&g_xr[(size_t)(row + 8) * HC + col] =
                    make_float2(acc[mt][nt][2], acc[mt][nt][3]);
            }
        }
    }
}

// ---------------- merged scan (self-resets g_deg) ----------------
__global__ void scan_kernel()            // 20 blocks x 1024
{
    __shared__ int wsum[32];
    __shared__ int sboff;
    int b = blockIdx.x, t = threadIdx.x;
    int i = b * 1024 + t;
    int v = (i < N_NODES) ? g_deg[i] : 0;
    if (i < N_NODES) g_deg[i] = 0;       // reset for next replay's histogram
    int lane = t & 31, w = t >> 5;
    int s = v;
#pragma unroll
    for (int o = 1; o < 32; o <<= 1) {
        int u = __shfl_up_sync(0xffffffffu, s, o);
        if (lane >= o) s += u;
    }
    if (lane == 31) wsum[w] = s;
    __syncthreads();
    if (w == 0) {
        int ws = wsum[lane];
#pragma unroll
        for (int o = 1; o < 32; o <<= 1) {
            int u = __shfl_up_sync(0xffffffffu, ws, o);
            if (lane >= o) ws += u;
        }
        wsum[lane] = ws;
    }
    __syncthreads();
    int excl = s - v + (w > 0 ? wsum[w - 1] : 0);
    if (t == 1023) g_bsum[b] = excl + v;
    __threadfence();

    if (t == 0) {
        atomicAdd(&g_c1, 1);
        while (atomicAdd(&g_c1, 0) < 20) {}
    }
    __syncthreads();

    if (t == 0) {
        int sum = 0;
        for (int j = 0; j < b; j++) sum += g_bsum[j];
        sboff = sum;
    }
    __syncthreads();
    if (i < N_NODES) {
        int o = excl + sboff;
        g_off[i] = o;
        g_cur[i] = o;
    }
    if (i == 0) g_off[N_NODES] = E_EDGES;

    if (t == 0) {
        int v2 = atomicAdd(&g_c2, 1);
        if (v2 == 19) { g_c1 = 0; g_c2 = 0; }
    }
}

__global__ void scatter_kernel(const int* __restrict__ ei)
{
    int e = blockIdx.x * blockDim.x + threadIdx.x;
    if (e < E_EDGES) {
        int d = ei[E_EDGES + e];
        int pos = atomicAdd(&g_cur[d], 1);
        g_csr_src[pos] = ei[e];
    }
}

// ---------------- GATv2 attention: 2 warps/node (head-split), 8-edge pipeline ----------------
__device__ __forceinline__ void load_row_bf8(uint32_t* d, int src, int c0) {
    uint4 a = *(const uint4*)&g_xlb[src * HC + c0];
    d[0] = a.x; d[1] = a.y; d[2] = a.z; d[3] = a.w;
}

__global__ void __launch_bounds__(256) attn_kernel(const float* __restrict__ att,
                                                   const float* __restrict__ bias)
{
    __shared__ float srow[4][512];

    const int wid  = threadIdx.x >> 5;
    const int lane = threadIdx.x & 31;
    const int node = wid >> 1;
    const int half = wid & 1;
    const int dst  = blockIdx.x * 4 + node;
    const int c0   = half * 256 + lane * 8;

    float xr_[8], at_[8];
    {
        const float4* p = (const float4*)&g_xr[dst * HC + c0];
        const float4* q = (const float4*)&att[c0];
#pragma unroll
        for (int k = 0; k < 2; k++) {
            float4 a = p[k]; float4 b = q[k];
            xr_[4*k+0] = a.x; xr_[4*k+1] = a.y; xr_[4*k+2] = a.z; xr_[4*k+3] = a.w;
            at_[4*k+0] = b.x; at_[4*k+1] = b.y; at_[4*k+2] = b.z; at_[4*k+3] = b.w;
        }
    }

    float m = -CUDART_INF_F;
    float s = 0.f;
    float acc[8];
#pragma unroll
    for (int j = 0; j < 8; j++) acc[j] = 0.f;

    const int beg = g_off[dst], end = g_off[dst + 1];

    uint32_t cur[8][4], nxt[8][4];
    if (beg < end) {
#pragma unroll
        for (int i = 0; i < 8; i++) {
            int idx = beg + i; if (idx > end - 1) idx = end - 1;
            load_row_bf8(cur[i], g_csr_src[idx], c0);
        }
    }

    for (int p = beg; p < end; p += 8) {
        bool have_next = (p + 8 < end);
        if (have_next) {
#pragma unroll
            for (int i = 0; i < 8; i++) {
                int idx = p + 8 + i; if (idx > end - 1) idx = end - 1;
                load_row_bf8(nxt[i], g_csr_src[idx], c0);
            }
        }

        float part[8];
#pragma unroll
        for (int i = 0; i < 8; i++) {
            float pt = 0.f;
#pragma unroll
            for (int j4 = 0; j4 < 4; j4++) {
                float x0 = bflo(cur[i][j4]);
                float x1 = bfhi(cur[i][j4]);
                float v0 = x0 + xr_[2*j4+0];
                float v1 = x1 + xr_[2*j4+1];
                float l0 = (v0 > 0.f) ? v0 : 0.2f * v0;
                float l1 = (v1 > 0.f) ? v1 : 0.2f * v1;
                pt = fmaf(l0, at_[2*j4+0], pt);
                pt = fmaf(l1, at_[2*j4+1], pt);
            }
            pt += __shfl_xor_sync(0xffffffffu, pt, 1);
            pt += __shfl_xor_sync(0xffffffffu, pt, 2);
            pt += __shfl_xor_sync(0xffffffffu, pt, 4);
            part[i] = (p + i < end) ? pt : -CUDART_INF_F;
        }

        float gm = part[0];
#pragma unroll
        for (int i = 1; i < 8; i++) gm = fmaxf(gm, part[i]);
        float mnew = fmaxf(m, gm);
        float corr = __expf(m - mnew);
        float w[8];
        float ws = 0.f;
#pragma unroll
        for (int i = 0; i < 8; i++) { w[i] = __expf(part[i] - mnew); ws += w[i]; }
        s = s * corr + ws;
#pragma unroll
        for (int j4 = 0; j4 < 4; j4++) {
            float t0 = acc[2*j4+0] * corr;
            float t1 = acc[2*j4+1] * corr;
#pragma unroll
            for (int i = 0; i < 8; i++) {
                t0 = fmaf(bflo(cur[i][j4]), w[i], t0);
                t1 = fmaf(bfhi(cur[i][j4]), w[i], t1);
            }
            acc[2*j4+0] = t0;
            acc[2*j4+1] = t1;
        }
        m = mnew;

        if (have_next) {
#pragma unroll
            for (int i = 0; i < 8; i++)
#pragma unroll
                for (int j4 = 0; j4 < 4; j4++) cur[i][j4] = nxt[i][j4];
        }
    }

    float inv = 1.f / (s + 1e-16f);
    const float4* bq = (const float4*)&bias[c0];
    uint32_t ob[4];
#pragma unroll
    for (int k = 0; k < 2; k++) {
        float4 b = bq[k];
        float4 o;
        o.x = fmaf(acc[4*k+0], inv, b.x);
        o.y = fmaf(acc[4*k+1], inv, b.y);
        o.z = fmaf(acc[4*k+2], inv, b.z);
        o.w = fmaf(acc[4*k+3], inv, b.w);
        *(float4*)&srow[node][c0 + 4*k] = o;
        ob[2*k + 0] = packbf(o.x, o.y);
        ob[2*k + 1] = packbf(o.z, o.w);
    }
    *(uint4*)&g_outb[dst * HC + c0] = make_uint4(ob[0], ob[1], ob[2], ob[3]);

    __syncthreads();
    {
        int t = threadIdx.x;
#pragma unroll
        for (int h = 0; h < 2; h++) {
            int c = t + h * 256;
            float ps = 0.f, pq = 0.f;
#pragma unroll
            for (int w2 = 0; w2 < 4; w2++) {
                float v = srow[w2][c];
                ps += v;
                pq = fmaf(v, v, pq);
            }
            g_ps[blockIdx.x * HC + c] = ps;
            g_pq[blockIdx.x * HC + c] = pq;
        }
    }
}

// ---------------- merged BN reduction ----------------
__global__ void bn_reduce_kernel(const float* __restrict__ gamma, const float* __restrict__ beta)
{
    int c = threadIdx.x;
    float s = 0.f, ss = 0.f;
    for (int r = blockIdx.x; r < ATTN_BLOCKS; r += BN1_BLOCKS) {
        s  += g_ps[r * HC + c];
        ss += g_pq[r * HC + c];
    }
    g_ps1[blockIdx.x * HC + c] = s;
    g_pq1[blockIdx.x * HC + c] = ss;
    __threadfence();

    __shared__ int last;
    if (threadIdx.x == 0) {
        int v = atomicAdd(&g_bn_cnt, 1);
        last = (v == BN1_BLOCKS - 1);
    }
    __syncthreads();
    if (last) {
        float t = 0.f, tt = 0.f;
        for (int b = 0; b < BN1_BLOCKS; b++) {
            t  += g_ps1[b * HC + c];
            tt += g_pq1[b * HC + c];
        }
        float mu  = t / (float)N_NODES;
        float var = tt / (float)N_NODES - mu * mu;
        float sc  = gamma[c] * rsqrtf(var + 1e-5f);
        g_scale[c] = sc;
        g_shift[c] = beta[c] - mu * sc;
        if (threadIdx.x == 0) g_bn_cnt = 0;
    }
}

// ---------------- link scoring: 2 pairs per warp, bf16 gathers + fused BN+ReLU ----------------
#define LINK_WARPS ((E_LABEL + 1) / 2)      // 50000
#define LINK_BLOCKS ((LINK_WARPS + 7) / 8)  // 6250

__global__ void link_kernel(const int* __restrict__ eli, float* __restrict__ out)
{
    int w = (blockIdx.x * blockDim.x + threadIdx.x) >> 5;
    int lane = threadIdx.x & 31;
    if (w >= LINK_WARPS) return;
    const int c0 = lane * 16;

    int p0 = 2 * w;
    int p1 = 2 * w + 1;
    bool has1 = (p1 < E_LABEL);
    int a0i = eli[p0];
    int b0i = eli[E_LABEL + p0];
    int a1i = has1 ? eli[p1] : a0i;
    int b1i = has1 ? eli[E_LABEL + p1] : b0i;

    uint4 ra0[2], rb0[2], ra1[2], rb1[2];
    ra0[0] = *(const uint4*)&g_outb[a0i * HC + c0];
    rb0[0] = *(const uint4*)&g_outb[b0i * HC + c0];
    ra1[0] = *(const uint4*)&g_outb[a1i * HC + c0];
    rb1[0] = *(const uint4*)&g_outb[b1i * HC + c0];
    ra0[1] = *(const uint4*)&g_outb[a0i * HC + c0 + 8];
    rb0[1] = *(const uint4*)&g_outb[b0i * HC + c0 + 8];
    ra1[1] = *(const uint4*)&g_outb[a1i * HC + c0 + 8];
    rb1[1] = *(const uint4*)&g_outb[b1i * HC + c0 + 8];

    float sc[16], sh[16];
    {
        const float4* psc = (const float4*)&g_scale[c0];
        const float4* psh = (const float4*)&g_shift[c0];
#pragma unroll
        for (int k = 0; k < 4; k++) {
            float4 c4 = psc[k], h4 = psh[k];
            sc[4*k+0] = c4.x; sc[4*k+1] = c4.y; sc[4*k+2] = c4.z; sc[4*k+3] = c4.w;
            sh[4*k+0] = h4.x; sh[4*k+1] = h4.y; sh[4*k+2] = h4.z; sh[4*k+3] = h4.w;
        }
    }

    float d0 = 0.f, d1 = 0.f;
#pragma unroll
    for (int h = 0; h < 2; h++) {
        uint32_t ua0[4] = {ra0[h].x, ra0[h].y, ra0[h].z, ra0[h].w};
        uint32_t ub0[4] = {rb0[h].x, rb0[h].y, rb0[h].z, rb0[h].w};
        uint32_t ua1[4] = {ra1[h].x, ra1[h].y, ra1[h].z, ra1[h].w};
        uint32_t ub1[4] = {rb1[h].x, rb1[h].y, rb1[h].z, rb1[h].w};
#pragma unroll
        for (int j = 0; j < 4; j++) {
            int cbase = h * 8 + 2 * j;
            float s0 = sc[cbase], s1 = sc[cbase + 1];
            float f0 = sh[cbase], f1 = sh[cbase + 1];
            float a0v = fmaxf(fmaf(bflo(ua0[j]), s0, f0), 0.f);
            float a1v = fmaxf(fmaf(bfhi(ua0[j]), s1, f1), 0.f);
            float b0v = fmaxf(fmaf(bflo(ub0[j]), s0, f0), 0.f);
            float b1v = fmaxf(fmaf(bfhi(ub0[j]), s1, f1), 0.f);
            d0 = fmaf(a0v, b0v, d0);
            d0 = fmaf(a1v, b1v, d0);
            float c0v = fmaxf(fmaf(bflo(ua1[j]), s0, f0), 0.f);
            float c1v = fmaxf(fmaf(bfhi(ua1[j]), s1, f1), 0.f);
            float e0v = fmaxf(fmaf(bflo(ub1[j]), s0, f0), 0.f);
            float e1v = fmaxf(fmaf(bfhi(ub1[j]), s1, f1), 0.f);
            d1 = fmaf(c0v, e0v, d1);
            d1 = fmaf(c1v, e1v, d1);
        }
    }
#pragma unroll
    for (int off = 16; off > 0; off >>= 1) {
        d0 += __shfl_xor_sync(0xffffffffu, d0, off);
        d1 += __shfl_xor_sync(0xffffffffu, d1, off);
    }
    if (lane == 0) {
        out[p0] = d0;
        if (has1) out[p1] = d1;
    }
}

// ---------------- launch ----------------
extern "C" void kernel_launch(void* const* d_in, const int* in_sizes, int n_in,
                              void* d_out, int out_size)
{
    const float* x     = (const float*)d_in[0];
    const int*   ei    = (const int*)  d_in[1];
    const int*   eli   = (const int*)  d_in[2];
    const float* W_l   = (const float*)d_in[3];
    const float* W_r   = (const float*)d_in[4];
    const float* att   = (const float*)d_in[5];
    const float* bias  = (const float*)d_in[6];
    const float* gamma = (const float*)d_in[7];
    const float* beta  = (const float*)d_in[8];
    float* out = (float*)d_out;

    static bool s_init = false;
    if (!s_init) {
        cudaFuncSetAttribute(gemm_tc_kernel,
                             cudaFuncAttributeMaxDynamicSharedMemorySize, GSMEM_TOTAL);
        s_init = true;
    }

    // #1 fused conversions + histogram (g_deg pre-zeroed by scan's self-reset)
    conv_fused_kernel<<<CONVX_BLOCKS + CONVW_BLOCKS + HIST_BLOCKS, 256>>>(x, W_l, W_r, ei);

    // #2 merged scan (also resets g_deg)
    scan_kernel<<<20, 1024>>>();

    // #3 single-pass fp16 GEMMs
    {
        dim3 g(HC / 128, N_PAD / 128, 2);
        gemm_tc_kernel<<<g, 256, GSMEM_TOTAL>>>();
    }

    // #4 full-grid scatter
    scatter_kernel<<<(E_EDGES + 255) / 256, 256>>>(ei);

    // #5 attention + aggregation, 2 warps/node, 8-edge pipeline (+ BN partials)
    attn_kernel<<<ATTN_BLOCKS, 256>>>(att, bias);

    // #6 merged BN reduction
    bn_reduce_kernel<<<BN1_BLOCKS, HC>>>(gamma, beta);

    // #7 link scoring, 2 pairs/warp, fused BN + ReLU
    link_kernel<<<LINK_BLOCKS, 256>>>(eli, out);
}

// round 15
// speedup vs baseline: 1.6200x; 1.6200x over previous
#include <cuda_runtime.h>
#include <cuda_bf16.h>
#include <cuda_fp16.h>
#include <math_constants.h>
#include <cstdint>

// Problem constants
#define N_NODES 20000
#define N_PAD   20096          // 157 * 128
#define IN_CH   512
#define HC      512
#define E_EDGES 320000
#define E_LABEL 100000
#define ATTN_BLOCKS 5000       // 20000 nodes / (8 warps / 2 warps-per-node)
#define BN1_BLOCKS 128

// ---------------- scratch ----------------
__device__ __half g_xh [N_PAD * IN_CH];        // fp16 x
__device__ __half g_wth[2][IN_CH * HC];        // fp16 W^T [n][k]
__device__ float g_xr[N_PAD * HC];
__device__ __nv_bfloat16 g_xlb[N_PAD * HC];    // bf16 xl
__device__ __nv_bfloat16 g_outb[N_NODES * HC]; // bf16 node features after GAT
__device__ int   g_deg[N_NODES + 1];           // zero at start; scan self-resets it
__device__ int   g_off[N_NODES + 1];
__device__ int   g_cur[N_NODES];
__device__ int   g_csr_src[E_EDGES];
__device__ int   g_bsum[32];
__device__ int   g_c1, g_c2;                   // scan grid-barrier counters (zero-init, self-reset)
__device__ int   g_bn_cnt;
__device__ float g_ps [ATTN_BLOCKS * HC];
__device__ float g_pq [ATTN_BLOCKS * HC];
__device__ float g_ps1[BN1_BLOCKS * HC];
__device__ float g_pq1[BN1_BLOCKS * HC];
__device__ float g_scale[HC];
__device__ float g_shift[HC];

// ---------------- helpers ----------------
__device__ __forceinline__ uint32_t smem_u32(const void* p) {
    uint32_t a;
    asm("{ .reg .u64 t; cvta.to.shared.u64 t, %1; cvt.u32.u64 %0, t; }" : "=r"(a) : "l"(p));
    return a;
}
__device__ __forceinline__ void cp_async16(uint32_t sa, const void* ga) {
    asm volatile("cp.async.cg.shared.global [%0], [%1], 16;" :: "r"(sa), "l"(ga) : "memory");
}
__device__ __forceinline__ void cp_commit() {
    asm volatile("cp.async.commit_group;" ::: "memory");
}
__device__ __forceinline__ void cp_wait0() {
    asm volatile("cp.async.wait_group 0;" ::: "memory");
}
__device__ __forceinline__ void ldm_x4(uint32_t* r, uint32_t addr) {
    asm volatile("ldmatrix.sync.aligned.m8n8.x4.shared.b16 {%0,%1,%2,%3}, [%4];"
                 : "=r"(r[0]), "=r"(r[1]), "=r"(r[2]), "=r"(r[3]) : "r"(addr));
}
__device__ __forceinline__ void mma16816h(float* d, const uint32_t* a, const uint32_t* b) {
    asm volatile("mma.sync.aligned.m16n8k16.row.col.f32.f16.f16.f32 "
                 "{%0,%1,%2,%3}, {%4,%5,%6,%7}, {%8,%9}, {%0,%1,%2,%3};"
                 : "+f"(d[0]), "+f"(d[1]), "+f"(d[2]), "+f"(d[3])
                 : "r"(a[0]), "r"(a[1]), "r"(a[2]), "r"(a[3]), "r"(b[0]), "r"(b[1]));
}
__device__ __forceinline__ float bflo(uint32_t u) { return __uint_as_float(u << 16); }
__device__ __forceinline__ float bfhi(uint32_t u) { return __uint_as_float(u & 0xFFFF0000u); }
__device__ __forceinline__ uint32_t packbf(float a, float b) {
    __nv_bfloat162 t = __float22bfloat162_rn(make_float2(a, b));
    return *(uint32_t*)&t;
}

// ---------------- fused conversion + histogram ----------------
#define CONVX_BLOCKS (N_PAD * IN_CH / 4 / 256)      // 10048
#define CONVW_BLOCKS (2 * IN_CH * HC / 256)         // 2048
#define HIST_BLOCKS  ((E_EDGES + 255) / 256)        // 1250

__global__ void conv_fused_kernel(const float* __restrict__ x,
                                  const float* __restrict__ Wl,
                                  const float* __restrict__ Wr,
                                  const int* __restrict__ ei)
{
    int bid = blockIdx.x;
    if (bid < CONVX_BLOCKS) {
        int i4 = bid * 256 + threadIdx.x;
        int i = i4 * 4;
        int row = i >> 9;
        float4 v = (row < N_NODES) ? *(const float4*)(x + i) : make_float4(0.f, 0.f, 0.f, 0.f);
        __half2 h01 = __floats2half2_rn(v.x, v.y);
        __half2 h23 = __floats2half2_rn(v.z, v.w);
        *(uint2*)((char*)g_xh + i * 2) = make_uint2(*(uint32_t*)&h01, *(uint32_t*)&h23);
    } else if (bid < CONVX_BLOCKS + CONVW_BLOCKS) {
        int j = (bid - CONVX_BLOCKS) * 256 + threadIdx.x;
        int mat = j >> 18;
        int i = j & 0x3FFFF;                                // n*512 + k
        const float* W = mat ? Wr : Wl;
        int n = i >> 9, k = i & 511;
        g_wth[mat][i] = __float2half_rn(W[k * HC + n]);
    } else {
        // histogram: g_deg is zero at kernel entry (zero-init + scan self-reset)
        int e = (bid - CONVX_BLOCKS - CONVW_BLOCKS) * 256 + threadIdx.x;
        if (e < E_EDGES) atomicAdd(&g_deg[ei[E_EDGES + e]], 1);
    }
}

// ---------------- single-pass fp16 HMMA GEMM (R12 proven) ----------------
#define SMS 144                      // 128B row + 16B pad
#define TILE_BYTES (128 * SMS)       // 18432
#define STAGE_BYTES (2 * TILE_BYTES) // 36864 (A + B tile)
#define GSMEM_TOTAL (2 * STAGE_BYTES)// 73728

__global__ void __launch_bounds__(256, 2) gemm_tc_kernel()
{
    extern __shared__ __align__(16) char smem[];

    const int tid  = threadIdx.x;
    const int wid  = tid >> 5;
    const int lane = tid & 31;
    const int wm   = wid & 1;
    const int wn   = wid >> 1;

    const int m0  = blockIdx.y * 128;
    const int n0  = blockIdx.x * 128;
    const int mat = blockIdx.z;

    const __half* A = g_xh + (size_t)m0 * IN_CH;
    const __half* B = g_wth[mat] + (size_t)n0 * IN_CH;

    const uint32_t sb = smem_u32(smem);
    const int r0 = tid >> 3;          // 0..31
    const int c0 = tid & 7;           // 16B chunk (0..7) within 128B row

    float acc[4][4][4];
#pragma unroll
    for (int i = 0; i < 4; i++)
#pragma unroll
        for (int j = 0; j < 4; j++)
#pragma unroll
            for (int q = 0; q < 4; q++) acc[i][j][q] = 0.f;

    auto issue = [&](int kc, int stg) {
        const uint32_t base = sb + stg * STAGE_BYTES;
        const int kel = kc * 64 + c0 * 8;
#pragma unroll
        for (int j = 0; j < 4; j++) {
            int row = r0 + j * 32;
            uint32_t so = row * SMS + c0 * 16;
            size_t  go = (size_t)row * IN_CH + kel;
            cp_async16(base + so, A + go);
            cp_async16(base + TILE_BYTES + so, B + go);
        }
    };

    issue(0, 0); cp_commit();

    for (int kc = 0; kc < 8; kc++) {
        cp_wait0();
        __syncthreads();
        if (kc + 1 < 8) { issue(kc + 1, (kc + 1) & 1); cp_commit(); }

        const uint32_t base = sb + (kc & 1) * STAGE_BYTES;
#pragma unroll
        for (int ks = 0; ks < 4; ks++) {
            const int kb = ks * 32;
            uint32_t b[4][2];
#pragma unroll
            for (int nh = 0; nh < 2; nh++) {
                int row = wn * 32 + nh * 16 + (lane >> 4) * 8 + (lane & 7);
                uint32_t off = row * SMS + kb + ((lane >> 3) & 1) * 16;
                uint32_t t[4];
                ldm_x4(t, base + TILE_BYTES + off);
                b[nh * 2 + 0][0] = t[0]; b[nh * 2 + 0][1] = t[1];
                b[nh * 2 + 1][0] = t[2]; b[nh * 2 + 1][1] = t[3];
            }
            uint32_t a[4][4];
            {
                int row = wm * 64 + ((lane >> 3) & 1) * 8 + (lane & 7);
                uint32_t off = row * SMS + kb + ((lane >> 4) & 1) * 16;
                ldm_x4(a[0], base + off);
            }
#pragma unroll
            for (int mt = 0; mt < 4; mt++) {
                if (mt < 3) {
                    int row = wm * 64 + (mt + 1) * 16 + ((lane >> 3) & 1) * 8 + (lane & 7);
                    uint32_t off = row * SMS + kb + ((lane >> 4) & 1) * 16;
                    ldm_x4(a[mt + 1], base + off);
                }
#pragma unroll
                for (int nt = 0; nt < 4; nt++)
                    mma16816h(acc[mt][nt], a[mt], b[nt]);
            }
        }
    }

    const int g = lane >> 2;
    const int q = lane & 3;
#pragma unroll
    for (int mt = 0; mt < 4; mt++) {
#pragma unroll
        for (int nt = 0; nt < 4; nt++) {
            int row = m0 + wm * 64 + mt * 16 + g;
            int col = n0 + wn * 32 + nt * 8 + q * 2;
            if (mat == 0) {
                *(uint32_t*)&g_xlb[(size_t)row * HC + col] =
                    packbf(acc[mt][nt][0], acc[mt][nt][1]);
                *(uint32_t*)&g_xlb[(size_t)(row + 8) * HC + col] =
                    packbf(acc[mt][nt][2], acc[mt][nt][3]);
            } else {
                *(float2*)&g_xr[(size_t)row * HC + col] =
                    make_float2(acc[mt][nt][0], acc[mt][nt][1]);
                *(float2*)&g_xr[(size_t)(row + 8) * HC + col] =
                    make_float2(acc[mt][nt][2], acc[mt][nt][3]);
            }
        }
    }
}

// ---------------- merged scan (self-resets g_deg) ----------------
__global__ void scan_kernel()            // 20 blocks x 1024
{
    __shared__ int wsum[32];
    __shared__ int sboff;
    int b = blockIdx.x, t = threadIdx.x;
    int i = b * 1024 + t;
    int v = (i < N_NODES) ? g_deg[i] : 0;
    if (i < N_NODES) g_deg[i] = 0;       // reset for next replay's histogram
    int lane = t & 31, w = t >> 5;
    int s = v;
#pragma unroll
    for (int o = 1; o < 32; o <<= 1) {
        int u = __shfl_up_sync(0xffffffffu, s, o);
        if (lane >= o) s += u;
    }
    if (lane == 31) wsum[w] = s;
    __syncthreads();
    if (w == 0) {
        int ws = wsum[lane];
#pragma unroll
        for (int o = 1; o < 32; o <<= 1) {
            int u = __shfl_up_sync(0xffffffffu, ws, o);
            if (lane >= o) ws += u;
        }
        wsum[lane] = ws;
    }
    __syncthreads();
    int excl = s - v + (w > 0 ? wsum[w - 1] : 0);
    if (t == 1023) g_bsum[b] = excl + v;
    __threadfence();

    if (t == 0) {
        atomicAdd(&g_c1, 1);
        while (atomicAdd(&g_c1, 0) < 20) {}
    }
    __syncthreads();

    if (t == 0) {
        int sum = 0;
        for (int j = 0; j < b; j++) sum += g_bsum[j];
        sboff = sum;
    }
    __syncthreads();
    if (i < N_NODES) {
        int o = excl + sboff;
        g_off[i] = o;
        g_cur[i] = o;
    }
    if (i == 0) g_off[N_NODES] = E_EDGES;

    if (t == 0) {
        int v2 = atomicAdd(&g_c2, 1);
        if (v2 == 19) { g_c1 = 0; g_c2 = 0; }
    }
}

__global__ void scatter_kernel(const int* __restrict__ ei)
{
    int e = blockIdx.x * blockDim.x + threadIdx.x;
    if (e < E_EDGES) {
        int d = ei[E_EDGES + e];
        int pos = atomicAdd(&g_cur[d], 1);
        g_csr_src[pos] = ei[e];
    }
}

// ---------------- GATv2 attention: 2 warps/node (head-split), 4-edge pipeline (R13 proven) ----------------
__device__ __forceinline__ void load_row_bf8(uint32_t* d, int src, int c0) {
    uint4 a = *(const uint4*)&g_xlb[src * HC + c0];
    d[0] = a.x; d[1] = a.y; d[2] = a.z; d[3] = a.w;
}

__global__ void __launch_bounds__(256) attn_kernel(const float* __restrict__ att,
                                                   const float* __restrict__ bias)
{
    __shared__ float srow[4][512];

    const int wid  = threadIdx.x >> 5;
    const int lane = threadIdx.x & 31;
    const int node = wid >> 1;
    const int half = wid & 1;
    const int dst  = blockIdx.x * 4 + node;
    const int c0   = half * 256 + lane * 8;

    float xr_[8], at_[8];
    {
        const float4* p = (const float4*)&g_xr[dst * HC + c0];
        const float4* q = (const float4*)&att[c0];
#pragma unroll
        for (int k = 0; k < 2; k++) {
            float4 a = p[k]; float4 b = q[k];
            xr_[4*k+0] = a.x; xr_[4*k+1] = a.y; xr_[4*k+2] = a.z; xr_[4*k+3] = a.w;
            at_[4*k+0] = b.x; at_[4*k+1] = b.y; at_[4*k+2] = b.z; at_[4*k+3] = b.w;
        }
    }

    float m = -CUDART_INF_F;
    float s = 0.f;
    float acc[8];
#pragma unroll
    for (int j = 0; j < 8; j++) acc[j] = 0.f;

    const int beg = g_off[dst], end = g_off[dst + 1];

    uint32_t cur[4][4], nxt[4][4];
    if (beg < end) {
#pragma unroll
        for (int i = 0; i < 4; i++) {
            int idx = beg + i; if (idx > end - 1) idx = end - 1;
            load_row_bf8(cur[i], g_csr_src[idx], c0);
        }
    }

    for (int p = beg; p < end; p += 4) {
        bool have_next = (p + 4 < end);
        if (have_next) {
#pragma unroll
            for (int i = 0; i < 4; i++) {
                int idx = p + 4 + i; if (idx > end - 1) idx = end - 1;
                load_row_bf8(nxt[i], g_csr_src[idx], c0);
            }
        }

        float part[4];
#pragma unroll
        for (int i = 0; i < 4; i++) {
            float pt = 0.f;
#pragma unroll
            for (int j4 = 0; j4 < 4; j4++) {
                float x0 = bflo(cur[i][j4]);
                float x1 = bfhi(cur[i][j4]);
                float v0 = x0 + xr_[2*j4+0];
                float v1 = x1 + xr_[2*j4+1];
                float l0 = (v0 > 0.f) ? v0 : 0.2f * v0;
                float l1 = (v1 > 0.f) ? v1 : 0.2f * v1;
                pt = fmaf(l0, at_[2*j4+0], pt);
                pt = fmaf(l1, at_[2*j4+1], pt);
            }
            pt += __shfl_xor_sync(0xffffffffu, pt, 1);
            pt += __shfl_xor_sync(0xffffffffu, pt, 2);
            pt += __shfl_xor_sync(0xffffffffu, pt, 4);
            part[i] = (p + i < end) ? pt : -CUDART_INF_F;
        }

        float gm = fmaxf(fmaxf(part[0], part[1]), fmaxf(part[2], part[3]));
        float mnew = fmaxf(m, gm);
        float corr = __expf(m - mnew);
        float w[4];
#pragma unroll
        for (int i = 0; i < 4; i++) w[i] = __expf(part[i] - mnew);
        s = s * corr + w[0] + w[1] + w[2] + w[3];
#pragma unroll
        for (int j4 = 0; j4 < 4; j4++) {
            float t0 = acc[2*j4+0] * corr;
            float t1 = acc[2*j4+1] * corr;
#pragma unroll
            for (int i = 0; i < 4; i++) {
                t0 = fmaf(bflo(cur[i][j4]), w[i], t0);
                t1 = fmaf(bfhi(cur[i][j4]), w[i], t1);
            }
            acc[2*j4+0] = t0;
            acc[2*j4+1] = t1;
        }
        m = mnew;

        if (have_next) {
#pragma unroll
            for (int i = 0; i < 4; i++)
#pragma unroll
                for (int j4 = 0; j4 < 4; j4++) cur[i][j4] = nxt[i][j4];
        }
    }

    float inv = 1.f / (s + 1e-16f);
    const float4* bq = (const float4*)&bias[c0];
    uint32_t ob[4];
#pragma unroll
    for (int k = 0; k < 2; k++) {
        float4 b = bq[k];
        float4 o;
        o.x = fmaf(acc[4*k+0], inv, b.x);
        o.y = fmaf(acc[4*k+1], inv, b.y);
        o.z = fmaf(acc[4*k+2], inv, b.z);
        o.w = fmaf(acc[4*k+3], inv, b.w);
        *(float4*)&srow[node][c0 + 4*k] = o;
        ob[2*k + 0] = packbf(o.x, o.y);
        ob[2*k + 1] = packbf(o.z, o.w);
    }
    *(uint4*)&g_outb[dst * HC + c0] = make_uint4(ob[0], ob[1], ob[2], ob[3]);

    __syncthreads();
    {
        int t = threadIdx.x;
#pragma unroll
        for (int h = 0; h < 2; h++) {
            int c = t + h * 256;
            float ps = 0.f, pq = 0.f;
#pragma unroll
            for (int w2 = 0; w2 < 4; w2++) {
                float v = srow[w2][c];
                ps += v;
                pq = fmaf(v, v, pq);
            }
            g_ps[blockIdx.x * HC + c] = ps;
            g_pq[blockIdx.x * HC + c] = pq;
        }
    }
}

// ---------------- merged BN reduction ----------------
__global__ void bn_reduce_kernel(const float* __restrict__ gamma, const float* __restrict__ beta)
{
    int c = threadIdx.x;
    float s = 0.f, ss = 0.f;
    for (int r = blockIdx.x; r < ATTN_BLOCKS; r += BN1_BLOCKS) {
        s  += g_ps[r * HC + c];
        ss += g_pq[r * HC + c];
    }
    g_ps1[blockIdx.x * HC + c] = s;
    g_pq1[blockIdx.x * HC + c] = ss;
    __threadfence();

    __shared__ int last;
    if (threadIdx.x == 0) {
        int v = atomicAdd(&g_bn_cnt, 1);
        last = (v == BN1_BLOCKS - 1);
    }
    __syncthreads();
    if (last) {
        float t = 0.f, tt = 0.f;
        for (int b = 0; b < BN1_BLOCKS; b++) {
            t  += g_ps1[b * HC + c];
            tt += g_pq1[b * HC + c];
        }
        float mu  = t / (float)N_NODES;
        float var = tt / (float)N_NODES - mu * mu;
        float sc  = gamma[c] * rsqrtf(var + 1e-5f);
        g_scale[c] = sc;
        g_shift[c] = beta[c] - mu * sc;
        if (threadIdx.x == 0) g_bn_cnt = 0;
    }
}

// ---------------- link scoring: bf16 gathers + fused BN+ReLU (R13 proven) ----------------
__global__ void link_kernel(const int* __restrict__ eli, float* __restrict__ out)
{
    int w = (blockIdx.x * blockDim.x + threadIdx.x) >> 5;
    int lane = threadIdx.x & 31;
    if (w >= E_LABEL) return;
    int a = eli[w];
    int b = eli[E_LABEL + w];
    const int c0 = lane * 16;
    const uint4* pa = (const uint4*)&g_outb[a * HC + c0];
    const uint4* pb = (const uint4*)&g_outb[b * HC + c0];
    uint4 a0 = pa[0], a1 = pa[1];
    uint4 b0 = pb[0], b1 = pb[1];
    uint32_t ua[8] = {a0.x, a0.y, a0.z, a0.w, a1.x, a1.y, a1.z, a1.w};
    uint32_t ub[8] = {b0.x, b0.y, b0.z, b0.w, b1.x, b1.y, b1.z, b1.w};
    const float4* psc = (const float4*)&g_scale[c0];
    const float4* psh = (const float4*)&g_shift[c0];
    float sc[16], sh[16];
#pragma unroll
    for (int k = 0; k < 4; k++) {
        float4 c4 = psc[k], h4 = psh[k];
        sc[4*k+0] = c4.x; sc[4*k+1] = c4.y; sc[4*k+2] = c4.z; sc[4*k+3] = c4.w;
        sh[4*k+0] = h4.x; sh[4*k+1] = h4.y; sh[4*k+2] = h4.z; sh[4*k+3] = h4.w;
    }
    float p = 0.f;
#pragma unroll
    for (int j8 = 0; j8 < 8; j8++) {
        float va0 = bflo(ua[j8]), va1 = bfhi(ua[j8]);
        float vb0 = bflo(ub[j8]), vb1 = bfhi(ub[j8]);
        float ax = fmaxf(fmaf(va0, sc[2*j8+0], sh[2*j8+0]), 0.f);
        float ay = fmaxf(fmaf(va1, sc[2*j8+1], sh[2*j8+1]), 0.f);
        float bx = fmaxf(fmaf(vb0, sc[2*j8+0], sh[2*j8+0]), 0.f);
        float by = fmaxf(fmaf(vb1, sc[2*j8+1], sh[2*j8+1]), 0.f);
        p = fmaf(ax, bx, p);
        p = fmaf(ay, by, p);
    }
#pragma unroll
    for (int off = 16; off > 0; off >>= 1)
        p += __shfl_xor_sync(0xffffffffu, p, off);
    if (lane == 0) out[w] = p;
}

// ---------------- launch ----------------
extern "C" void kernel_launch(void* const* d_in, const int* in_sizes, int n_in,
                              void* d_out, int out_size)
{
    const float* x     = (const float*)d_in[0];
    const int*   ei    = (const int*)  d_in[1];
    const int*   eli   = (const int*)  d_in[2];
    const float* W_l   = (const float*)d_in[3];
    const float* W_r   = (const float*)d_in[4];
    const float* att   = (const float*)d_in[5];
    const float* bias  = (const float*)d_in[6];
    const float* gamma = (const float*)d_in[7];
    const float* beta  = (const float*)d_in[8];
    float* out = (float*)d_out;

    static bool s_init = false;
    if (!s_init) {
        cudaFuncSetAttribute(gemm_tc_kernel,
                             cudaFuncAttributeMaxDynamicSharedMemorySize, GSMEM_TOTAL);
        s_init = true;
    }

    // #1 fused conversions + histogram (g_deg pre-zeroed by scan's self-reset)
    conv_fused_kernel<<<CONVX_BLOCKS + CONVW_BLOCKS + HIST_BLOCKS, 256>>>(x, W_l, W_r, ei);

    // #2 merged scan (also resets g_deg)
    scan_kernel<<<20, 1024>>>();

    // #3 single-pass fp16 GEMMs
    {
        dim3 g(HC / 128, N_PAD / 128, 2);
        gemm_tc_kernel<<<g, 256, GSMEM_TOTAL>>>();
    }

    // #4 full-grid scatter
    scatter_kernel<<<(E_EDGES + 255) / 256, 256>>>(ei);

    // #5 attention + aggregation, 2 warps/node, 4-edge pipeline (+ BN partials)
    attn_kernel<<<ATTN_BLOCKS, 256>>>(att, bias);

    // #6 merged BN reduction
    bn_reduce_kernel<<<BN1_BLOCKS, HC>>>(gamma, beta);

    // #7 link scoring with fused BN + ReLU
    link_kernel<<<(E_LABEL * 32) / 256, 256>>>(eli, out);
}